// round 7
// baseline (speedup 1.0000x reference)
#include <cuda_runtime.h>

// CplxGaussianRBF: out[b,c,p,{re,im}] = sum_w exp(-|x[b,c,p]-mu[w]|^2/(2*sd[w])) * w_{re,im}[c,w] + bias
// B=4, C=32, H=W=64 (HW=4096), NW=64.
//
// R6: R5 showed L1/LDS as the binder (64.5%) — 3 broadcast LDS.128 per weight for
// only 2 pixels. Now 4 pixels/thread (two f32x2 streams): same 3 coefficient loads
// amortize over twice the compute, halving LDS per pixel. MUFU (1 ex2 per
// pixel-weight, irreducible) becomes the floor (~7.3us). Exponent kept in the
// A*n + B*xr + C*xi + D form (3 FFMA2/stream), coefficients pre-duplicated in smem
// ({A,A,B,B},{C,C,D,D},{wr,wr,wi,wi}) so LDS.128 yields packed f32x2 operands.

#define CN   32
#define HWN  4096
#define NWN  64

__device__ __forceinline__ unsigned long long fma2(unsigned long long a,
                                                   unsigned long long b,
                                                   unsigned long long c) {
    unsigned long long d;
    asm("fma.rn.f32x2 %0, %1, %2, %3;" : "=l"(d) : "l"(a), "l"(b), "l"(c));
    return d;
}
__device__ __forceinline__ unsigned long long pack2(float lo, float hi) {
    unsigned long long d;
    asm("mov.b64 %0, {%1, %2};" : "=l"(d) : "f"(lo), "f"(hi));
    return d;
}
__device__ __forceinline__ void unpack2(unsigned long long v, float& lo, float& hi) {
    asm("mov.b64 {%0, %1}, %2;" : "=f"(lo), "=f"(hi) : "l"(v));
}
__device__ __forceinline__ unsigned long long ex2_2(unsigned long long v) {
    float t0, t1;
    unpack2(v, t0, t1);
    float e0, e1;
    asm("ex2.approx.f32 %0, %1;" : "=f"(e0) : "f"(t0));
    asm("ex2.approx.f32 %0, %1;" : "=f"(e1) : "f"(t1));
    return pack2(e0, e1);
}

__global__ __launch_bounds__(256)
void cplx_rbf_kernel(
    const float* __restrict__ xr, const float* __restrict__ xi,
    const float* __restrict__ wr, const float* __restrict__ wi,
    const float* __restrict__ br, const float* __restrict__ bi,
    const float* __restrict__ mur, const float* __restrict__ mui,
    const float* __restrict__ sd,
    float* __restrict__ out)
{
    // per weight w: s_ab = {A,A,B,B}, s_cd = {C,C,D,D}, s_wp = {wr,wr,wi,wi}
    __shared__ __align__(16) float s_ab[NWN * 4];
    __shared__ __align__(16) float s_cd[NWN * 4];
    __shared__ __align__(16) float s_wp[NWN * 4];

    const int t  = threadIdx.x;
    const int bc = blockIdx.x >> 2;           // (b*C + c) slice index (4 blocks/slice)
    const int c  = bc & (CN - 1);

    if (t < NWN) {
        const float cf = -0.7213475204444817f / sd[t];   // -log2(e)/(2*sd)
        const float mr = mur[t];
        const float mi = mui[t];
        const float A  = cf;
        const float Bq = -2.0f * cf * mr;
        const float Cq = -2.0f * cf * mi;
        const float D  = cf * fmaf(mr, mr, mi * mi);
        const float wrv = wr[c * NWN + t];
        const float wiv = wi[c * NWN + t];
        reinterpret_cast<float4*>(s_ab)[t] = make_float4(A,  A,  Bq, Bq);
        reinterpret_cast<float4*>(s_cd)[t] = make_float4(Cq, Cq, D,  D);
        reinterpret_cast<float4*>(s_wp)[t] = make_float4(wrv, wrv, wiv, wiv);
    }
    __syncthreads();

    const int p0   = ((blockIdx.x & 3) << 10) + (t << 2);  // 4 pixels per thread
    const int base = bc * HWN;

    const float4 x_r = *reinterpret_cast<const float4*>(xr + base + p0);
    const float4 x_i = *reinterpret_cast<const float4*>(xi + base + p0);

    const unsigned long long xrA = pack2(x_r.x, x_r.y);
    const unsigned long long xiA = pack2(x_i.x, x_i.y);
    const unsigned long long xrB = pack2(x_r.z, x_r.w);
    const unsigned long long xiB = pack2(x_i.z, x_i.w);
    const unsigned long long nA  = pack2(fmaf(x_r.x, x_r.x, x_i.x * x_i.x),
                                         fmaf(x_r.y, x_r.y, x_i.y * x_i.y));
    const unsigned long long nB  = pack2(fmaf(x_r.z, x_r.z, x_i.z * x_i.z),
                                         fmaf(x_r.w, x_r.w, x_i.w * x_i.w));

    unsigned long long accrA = 0ULL, acciA = 0ULL;   // {0.f,0.f}
    unsigned long long accrB = 0ULL, acciB = 0ULL;

    const ulonglong2* ab2 = reinterpret_cast<const ulonglong2*>(s_ab);
    const ulonglong2* cd2 = reinterpret_cast<const ulonglong2*>(s_cd);
    const ulonglong2* wp2 = reinterpret_cast<const ulonglong2*>(s_wp);

#pragma unroll
    for (int w = 0; w < NWN; w++) {
        const ulonglong2 ab = ab2[w];   // .x = {A,A},   .y = {B,B}
        const ulonglong2 cd = cd2[w];   // .x = {C,C},   .y = {D,D}
        const ulonglong2 wp = wp2[w];   // .x = {wr,wr}, .y = {wi,wi}

        unsigned long long eA = fma2(ab.x, nA, cd.y);    // A*n + D
        unsigned long long eB = fma2(ab.x, nB, cd.y);
        eA = fma2(ab.y, xrA, eA);                        // + B*xr
        eB = fma2(ab.y, xrB, eB);
        eA = fma2(cd.x, xiA, eA);                        // + C*xi
        eB = fma2(cd.x, xiB, eB);

        const unsigned long long gA = ex2_2(eA);
        const unsigned long long gB = ex2_2(eB);

        accrA = fma2(gA, wp.x, accrA);
        acciA = fma2(gA, wp.y, acciA);
        accrB = fma2(gB, wp.x, accrB);
        acciB = fma2(gB, wp.y, acciB);
    }

    float ar0, ar1, ar2, ar3, ai0, ai1, ai2, ai3;
    unpack2(accrA, ar0, ar1);
    unpack2(acciA, ai0, ai1);
    unpack2(accrB, ar2, ar3);
    unpack2(acciB, ai2, ai3);

    const float brc = br[c];
    const float bic = bi[c];

    float4 o0, o1;
    o0.x = ar0 + brc;  o0.y = ai0 + bic;   // pixel p0
    o0.z = ar1 + brc;  o0.w = ai1 + bic;   // pixel p0+1
    o1.x = ar2 + brc;  o1.y = ai2 + bic;   // pixel p0+2
    o1.z = ar3 + brc;  o1.w = ai3 + bic;   // pixel p0+3
    float* op = out + (size_t)(base + p0) * 2;
    *reinterpret_cast<float4*>(op)     = o0;
    *reinterpret_cast<float4*>(op + 4) = o1;
}

extern "C" void kernel_launch(void* const* d_in, const int* in_sizes, int n_in,
                              void* d_out, int out_size)
{
    const float* xr  = (const float*)d_in[0];  // x_real  (4,32,64,64)
    const float* xi  = (const float*)d_in[1];  // x_imag
    const float* wr  = (const float*)d_in[2];  // w_real  (32,64)
    const float* wi  = (const float*)d_in[3];  // w_imag
    const float* br  = (const float*)d_in[4];  // b_real  (1,32,1)
    const float* bi  = (const float*)d_in[5];  // b_imag
    const float* mur = (const float*)d_in[6];  // mu_real (64)
    const float* mui = (const float*)d_in[7];  // mu_imag (64)
    const float* sd  = (const float*)d_in[8];  // stddev  (64)
    float* out = (float*)d_out;                // (4,32,64,64,2)

    // 4*32*4096 pixels / (256 threads * 4 pixels) = 512 blocks
    cplx_rbf_kernel<<<512, 256>>>(xr, xi, wr, wi, br, bi, mur, mui, sd, out);
}

// round 8
// speedup vs baseline: 1.2691x; 1.2691x over previous
#include <cuda_runtime.h>

// CplxGaussianRBF: out[b,c,p,{re,im}] = sum_w exp(-|x[b,c,p]-mu[w]|^2/(2*sd[w])) * w_{re,im}[c,w] + bias
// B=4, C=32, H=W=64 (HW=4096), NW=64.
//
// R7: pack WEIGHT PAIRS (w, w+1) into f32x2 lanes instead of pixel pairs.
// Coefficients then need no duplication in smem: one LDS.128 = {A_w,A_w+1,B_w,B_w+1}
// is two ready packed operands -> 1.5 LDS.128 per weight (was 3). Per-pixel values
// (xr, xi, n=|x|^2) are duplicated into {v,v} once per thread. 2 pixels/thread keeps
// 8192 warps (occ ~68%, the R5 level that R6 lost). Exponent = A*n + B*xr + C*xi + D
// (3 FFMA2 per pixel per weight-pair). Accumulators are f32x2 over (even,odd) weights;
// final horizontal add folds them. MUFU (1 ex2 per pixel-weight) is the ~7.4us floor.

#define CN   32
#define HWN  4096
#define NWN  64

__device__ __forceinline__ unsigned long long fma2(unsigned long long a,
                                                   unsigned long long b,
                                                   unsigned long long c) {
    unsigned long long d;
    asm("fma.rn.f32x2 %0, %1, %2, %3;" : "=l"(d) : "l"(a), "l"(b), "l"(c));
    return d;
}
__device__ __forceinline__ unsigned long long pack2(float lo, float hi) {
    unsigned long long d;
    asm("mov.b64 %0, {%1, %2};" : "=l"(d) : "f"(lo), "f"(hi));
    return d;
}
__device__ __forceinline__ void unpack2(unsigned long long v, float& lo, float& hi) {
    asm("mov.b64 {%0, %1}, %2;" : "=f"(lo), "=f"(hi) : "l"(v));
}
__device__ __forceinline__ unsigned long long ex2_2(unsigned long long v) {
    float t0, t1;
    unpack2(v, t0, t1);
    float e0, e1;
    asm("ex2.approx.f32 %0, %1;" : "=f"(e0) : "f"(t0));
    asm("ex2.approx.f32 %0, %1;" : "=f"(e1) : "f"(t1));
    return pack2(e0, e1);
}

__global__ __launch_bounds__(256)
void cplx_rbf_kernel(
    const float* __restrict__ xr, const float* __restrict__ xi,
    const float* __restrict__ wr, const float* __restrict__ wi,
    const float* __restrict__ br, const float* __restrict__ bi,
    const float* __restrict__ mur, const float* __restrict__ mui,
    const float* __restrict__ sd,
    float* __restrict__ out)
{
    // Per weight-pair j (weights 2j, 2j+1):
    //   s_ab[j] = {A0, A1, B0, B1}
    //   s_cd[j] = {C0, C1, D0, D1}
    //   s_wp[j] = {wr0, wr1, wi0, wi1}
    __shared__ __align__(16) float s_ab[NWN * 2];
    __shared__ __align__(16) float s_cd[NWN * 2];
    __shared__ __align__(16) float s_wp[NWN * 2];

    const int t  = threadIdx.x;
    const int bc = blockIdx.x >> 3;           // (b*C + c) slice index (8 blocks/slice)
    const int c  = bc & (CN - 1);

    if (t < NWN / 2) {
        const int w0 = 2 * t, w1 = 2 * t + 1;
        const float cf0 = -0.7213475204444817f / sd[w0];   // -log2(e)/(2*sd)
        const float cf1 = -0.7213475204444817f / sd[w1];
        const float mr0 = mur[w0], mi0 = mui[w0];
        const float mr1 = mur[w1], mi1 = mui[w1];
        reinterpret_cast<float4*>(s_ab)[t] =
            make_float4(cf0, cf1, -2.0f * cf0 * mr0, -2.0f * cf1 * mr1);
        reinterpret_cast<float4*>(s_cd)[t] =
            make_float4(-2.0f * cf0 * mi0, -2.0f * cf1 * mi1,
                        cf0 * fmaf(mr0, mr0, mi0 * mi0),
                        cf1 * fmaf(mr1, mr1, mi1 * mi1));
        reinterpret_cast<float4*>(s_wp)[t] =
            make_float4(wr[c * NWN + w0], wr[c * NWN + w1],
                        wi[c * NWN + w0], wi[c * NWN + w1]);
    }
    __syncthreads();

    const int p0   = ((blockIdx.x & 7) << 9) + (t << 1);   // 2 pixels per thread
    const int base = bc * HWN;

    const float2 x_r = *reinterpret_cast<const float2*>(xr + base + p0);
    const float2 x_i = *reinterpret_cast<const float2*>(xi + base + p0);

    // duplicated per-pixel packed values
    const unsigned long long xr0d = pack2(x_r.x, x_r.x);
    const unsigned long long xi0d = pack2(x_i.x, x_i.x);
    const unsigned long long xr1d = pack2(x_r.y, x_r.y);
    const unsigned long long xi1d = pack2(x_i.y, x_i.y);
    const float n0 = fmaf(x_r.x, x_r.x, x_i.x * x_i.x);
    const float n1 = fmaf(x_r.y, x_r.y, x_i.y * x_i.y);
    const unsigned long long n0d = pack2(n0, n0);
    const unsigned long long n1d = pack2(n1, n1);

    // accumulators: {sum over even w, sum over odd w}
    unsigned long long accr0 = 0ULL, acci0 = 0ULL;
    unsigned long long accr1 = 0ULL, acci1 = 0ULL;

    const ulonglong2* ab2 = reinterpret_cast<const ulonglong2*>(s_ab);
    const ulonglong2* cd2 = reinterpret_cast<const ulonglong2*>(s_cd);
    const ulonglong2* wp2 = reinterpret_cast<const ulonglong2*>(s_wp);

#pragma unroll
    for (int j = 0; j < NWN / 2; j++) {
        const ulonglong2 ab = ab2[j];   // .x = {A0,A1},   .y = {B0,B1}
        const ulonglong2 cd = cd2[j];   // .x = {C0,C1},   .y = {D0,D1}
        const ulonglong2 wp = wp2[j];   // .x = {wr0,wr1}, .y = {wi0,wi1}

        unsigned long long e0 = fma2(ab.x, n0d, cd.y);   // A*n + D
        unsigned long long e1 = fma2(ab.x, n1d, cd.y);
        e0 = fma2(ab.y, xr0d, e0);                       // + B*xr
        e1 = fma2(ab.y, xr1d, e1);
        e0 = fma2(cd.x, xi0d, e0);                       // + C*xi
        e1 = fma2(cd.x, xi1d, e1);

        const unsigned long long g0 = ex2_2(e0);
        const unsigned long long g1 = ex2_2(e1);

        accr0 = fma2(g0, wp.x, accr0);
        acci0 = fma2(g0, wp.y, acci0);
        accr1 = fma2(g1, wp.x, accr1);
        acci1 = fma2(g1, wp.y, acci1);
    }

    float a, b2;
    const float brc = br[c];
    const float bic = bi[c];

    float4 o;
    unpack2(accr0, a, b2);  o.x = a + b2 + brc;   // pixel p0   real
    unpack2(acci0, a, b2);  o.y = a + b2 + bic;   // pixel p0   imag
    unpack2(accr1, a, b2);  o.z = a + b2 + brc;   // pixel p0+1 real
    unpack2(acci1, a, b2);  o.w = a + b2 + bic;   // pixel p0+1 imag
    *reinterpret_cast<float4*>(out + (size_t)(base + p0) * 2) = o;
}

extern "C" void kernel_launch(void* const* d_in, const int* in_sizes, int n_in,
                              void* d_out, int out_size)
{
    const float* xr  = (const float*)d_in[0];  // x_real  (4,32,64,64)
    const float* xi  = (const float*)d_in[1];  // x_imag
    const float* wr  = (const float*)d_in[2];  // w_real  (32,64)
    const float* wi  = (const float*)d_in[3];  // w_imag
    const float* br  = (const float*)d_in[4];  // b_real  (1,32,1)
    const float* bi  = (const float*)d_in[5];  // b_imag
    const float* mur = (const float*)d_in[6];  // mu_real (64)
    const float* mui = (const float*)d_in[7];  // mu_imag (64)
    const float* sd  = (const float*)d_in[8];  // stddev  (64)
    float* out = (float*)d_out;                // (4,32,64,64,2)

    // 4*32*4096 pixels / (256 threads * 2 pixels) = 1024 blocks
    cplx_rbf_kernel<<<1024, 256>>>(xr, xi, wr, wi, br, bi, mur, mui, sd, out);
}